// round 16
// baseline (speedup 1.0000x reference)
#include <cuda_runtime.h>
#include <cuda_bf16.h>
#include <cuda_fp16.h>
#include <cstdint>

#define NN 50000
#define EE 800000
#define DD 128
#define NMAT (DD*DD)
#define CAP 96                   // bucket capacity (max degree; Poisson(16) -> safe)
#define CVB 1563                 // x->fp16 conversion blocks
#define ZB  25                   // cursor zero blocks

#define AST 136                  // padded row stride (fp16 elems) -> conflict-free ldmatrix
#define PL  (128*AST)            // plane elems (17408)
#define PLB (PL*2)               // plane bytes (34816)

// ---------------- scratch (static device globals; no runtime alloc) ----------------
__device__ __half g_xh[NN*DD];    // fp16 copy of x
__device__ __half g_x1h[NN*DD];   // fp16 layer-1 activations
__device__ __half g_aggh[NN*DD];  // fp16 aggregation output
__device__ int    g_cursor[NN];   // zeroed by k_prep each run; after scatter holds degree
__device__ int    g_csr[NN*CAP];
__device__ __half g_Wh[5*PL];     // 5 matrices, fp16 plane, padded layout

// ---------------- helpers ----------------
__device__ __forceinline__ uint32_t smem_u32(const void* p) {
    uint32_t a;
    asm("{ .reg .u64 t; cvta.to.shared.u64 t, %1; cvt.u32.u64 %0, t; }" : "=r"(a) : "l"(p));
    return a;
}

#define LDSM4(r, addr) \
    asm volatile("ldmatrix.sync.aligned.m8n8.x4.shared.b16 {%0,%1,%2,%3}, [%4];" \
        : "=r"((r)[0]), "=r"((r)[1]), "=r"((r)[2]), "=r"((r)[3]) : "r"(addr))

#define MMAH(d, a, b0, b1) \
    asm volatile("mma.sync.aligned.m16n8k16.row.col.f32.f16.f16.f32 " \
        "{%0,%1,%2,%3}, {%4,%5,%6,%7}, {%8,%9}, {%0,%1,%2,%3};" \
        : "+f"((d)[0]), "+f"((d)[1]), "+f"((d)[2]), "+f"((d)[3]) \
        : "r"((a)[0]), "r"((a)[1]), "r"((a)[2]), "r"((a)[3]), "r"(b0), "r"(b1))

// per-block edge_index dtype detection (JAX x64-off downcasts int64 -> int32)
__device__ __forceinline__ int detect_is64(const void* __restrict__ ei) {
    __shared__ int s64;
    if (threadIdx.x < 32) {
        const long long* p = (const long long*)ei;
        long long v0 = p[threadIdx.x];
        long long v1 = p[threadIdx.x + 32];
        unsigned ok = (v0 >= 0 && v0 < NN && v1 >= 0 && v1 < NN) ? 1u : 0u;
        unsigned m = __ballot_sync(0xffffffffu, ok);
        if (threadIdx.x == 0) s64 = (m == 0xffffffffu) ? 1 : 0;
    }
    __syncthreads();
    return s64;
}
__device__ __forceinline__ int load_idx(const void* ei, int pos, int is64) {
    if (is64) return (int)((const long long*)ei)[pos];
    return ((const int*)ei)[pos];
}

// ---------------- prep: x->fp16 copy, zero cursor, weight fp16 image ----------------
__global__ void k_prep(const float* __restrict__ x,
                       const float* __restrict__ Wl, const float* __restrict__ Wr,
                       const float* __restrict__ W) {
    int b = blockIdx.x;
    if (b < CVB) {
        int i = (b*512 + threadIdx.x) * 8;
        if (i < NN*DD) {
            float4 v0 = ((const float4*)x)[i/4];
            float4 v1 = ((const float4*)x)[i/4 + 1];
            __half2 h0 = __floats2half2_rn(v0.x, v0.y);
            __half2 h1 = __floats2half2_rn(v0.z, v0.w);
            __half2 h2 = __floats2half2_rn(v1.x, v1.y);
            __half2 h3 = __floats2half2_rn(v1.z, v1.w);
            uint4 o;
            o.x = *(unsigned*)&h0; o.y = *(unsigned*)&h1;
            o.z = *(unsigned*)&h2; o.w = *(unsigned*)&h3;
            ((uint4*)g_xh)[i/8] = o;
        }
    } else if (b < CVB + ZB) {
        int i = ((b - CVB)*512 + threadIdx.x) * 4;
        if (i < NN) ((int4*)g_cursor)[i/4] = make_int4(0,0,0,0);
    } else {
        int m = b - CVB - ZB;   // 0,1=Wl 2,3=Wr 4=W
        const float* src = (m < 2) ? Wl + m*NMAT : ((m < 4) ? Wr + (m-2)*NMAT : W);
        __half* dst = g_Wh + (size_t)m*PL;
        for (int idx = threadIdx.x; idx < NMAT; idx += blockDim.x) {
            int row = idx >> 7, k = idx & 127;
            dst[row*AST + k] = __float2half_rn(src[idx]);
        }
    }
}

// ---------------- bucket scatter (no count/scan needed) ----------------
__global__ void k_scatter(const void* __restrict__ ei) {
    int is64 = detect_is64(ei);
    int i = blockIdx.x*blockDim.x + threadIdx.x;
    if (i < EE) {
        int src = load_idx(ei, i, is64);
        int dst = load_idx(ei, EE + i, is64);
        if ((unsigned)dst < NN && (unsigned)src < NN) {
            int pos = atomicAdd(&g_cursor[dst], 1);
            if (pos < CAP) g_csr[dst*CAP + pos] = src;
        }
    }
}

// ---------------- max-aggregation over fp16 copy: warp per node ----------------
__global__ void k_agg_h(const __half* __restrict__ xh, __half* __restrict__ aggh) {
    int w    = blockIdx.x * 8 + (threadIdx.x >> 5);
    int lane = threadIdx.x & 31;
    if (w >= NN) return;
    int cnt = g_cursor[w];
    if (cnt > CAP) cnt = CAP;
    const int* bucket = g_csr + w*CAP;
    const uint2* xv = (const uint2*)xh;     // 4 fp16 per lane
    const float NEG = __int_as_float(0xff800000);
    float4 m = make_float4(NEG, NEG, NEG, NEG);
    int e = 0;
    for (; e + 8 <= cnt; e += 8) {
        int s0 = bucket[e],   s1 = bucket[e+1], s2 = bucket[e+2], s3 = bucket[e+3];
        int s4 = bucket[e+4], s5 = bucket[e+5], s6 = bucket[e+6], s7 = bucket[e+7];
        uint2 u0 = xv[s0*32 + lane], u1 = xv[s1*32 + lane];
        uint2 u2 = xv[s2*32 + lane], u3 = xv[s3*32 + lane];
        uint2 u4 = xv[s4*32 + lane], u5 = xv[s5*32 + lane];
        uint2 u6 = xv[s6*32 + lane], u7 = xv[s7*32 + lane];
        #pragma unroll
        for (int j = 0; j < 8; j++) {
            uint2 u = (j==0)?u0:(j==1)?u1:(j==2)?u2:(j==3)?u3:(j==4)?u4:(j==5)?u5:(j==6)?u6:u7;
            float2 a = __half22float2(*(__half2*)&u.x);
            float2 bq = __half22float2(*(__half2*)&u.y);
            m.x = fmaxf(m.x, a.x);  m.y = fmaxf(m.y, a.y);
            m.z = fmaxf(m.z, bq.x); m.w = fmaxf(m.w, bq.y);
        }
    }
    for (; e < cnt; e++) {
        uint2 u = xv[bucket[e]*32 + lane];
        float2 a = __half22float2(*(__half2*)&u.x);
        float2 bq = __half22float2(*(__half2*)&u.y);
        m.x = fmaxf(m.x, a.x);  m.y = fmaxf(m.y, a.y);
        m.z = fmaxf(m.z, bq.x); m.w = fmaxf(m.w, bq.y);
    }
    if (cnt == 0) m = make_float4(0.f, 0.f, 0.f, 0.f);
    __half2 h01 = __floats2half2_rn(m.x, m.y);
    __half2 h23 = __floats2half2_rn(m.z, m.w);
    uint2 o;
    o.x = *(unsigned*)&h01; o.y = *(unsigned*)&h23;
    ((uint2*)aggh)[w*32 + lane] = o;
}

// ---------------- all-fp16 tensor-core GEMM ----------------
// MODE 0: out_h = relu( A1 @ W1^T + A2 @ W2^T + bias1 )            (fp16 out)
//         TM=64-row tiles, 256 threads, smem 104448 -> 2 CTAs/SM (phase overlap)
// MODE 1: t = relu(...); out_f = t @ W3^T + bias2 (fp32)
//         TM=128-row tiles, 512 threads, 1 CTA/SM (W3 resident)
// warp tile 32x32 in both; persistent grid.

template<int TM, int THREADS>
__device__ __forceinline__ void copy_tile_h(const __half* __restrict__ src, char* plane,
                                            int row0, int nrows) {
    int tid = threadIdx.x;
    #pragma unroll
    for (int it = 0; it < (TM*16)/THREADS; it++) {
        int fidx = it*THREADS + tid;        // TM*16 uint4s
        int row = fidx >> 4;
        int c   = fidx & 15;
        uint4 v = make_uint4(0,0,0,0);
        if (row0 + row < nrows) v = ((const uint4*)src)[(row0 + row)*16 + c];
        *(uint4*)(plane + row*(AST*2) + c*16) = v;
    }
}

// acc += A1 @ W1^T + A2 @ W2^T, interleaved per k-step
__device__ __forceinline__ void pass_dual(float acc[2][4][4],
                                          uint32_t aPl1, uint32_t aPl2,
                                          uint32_t wPl1, uint32_t wPl2,
                                          const uint32_t* aoff, const uint32_t* woff) {
    #pragma unroll 1
    for (int ks = 0; ks < 8; ks++) {
        uint32_t kb = (uint32_t)ks * 32u;
        uint32_t a1[2][4], a2[2][4], w1[2][4], w2[2][4];
        #pragma unroll
        for (int mt = 0; mt < 2; mt++) {
            LDSM4(a1[mt], aPl1 + aoff[mt] + kb);
            LDSM4(a2[mt], aPl2 + aoff[mt] + kb);
        }
        #pragma unroll
        for (int c = 0; c < 2; c++) {
            LDSM4(w1[c], wPl1 + woff[c] + kb);
            LDSM4(w2[c], wPl2 + woff[c] + kb);
        }
        #pragma unroll
        for (int mt = 0; mt < 2; mt++) {
            #pragma unroll
            for (int c = 0; c < 2; c++) {
                MMAH(acc[mt][2*c],   a1[mt], w1[c][0], w1[c][1]);
                MMAH(acc[mt][2*c+1], a1[mt], w1[c][2], w1[c][3]);
                MMAH(acc[mt][2*c],   a2[mt], w2[c][0], w2[c][1]);
                MMAH(acc[mt][2*c+1], a2[mt], w2[c][2], w2[c][3]);
            }
        }
    }
}

// acc += A @ W^T (single stream; chained W3 pass)
__device__ __forceinline__ void pass_h(float acc[2][4][4],
                                       uint32_t aPl, uint32_t wPl,
                                       const uint32_t* aoff, const uint32_t* woff) {
    #pragma unroll 2
    for (int ks = 0; ks < 8; ks++) {
        uint32_t kb = (uint32_t)ks * 32u;
        uint32_t a[2][4], w[2][4];
        #pragma unroll
        for (int mt = 0; mt < 2; mt++) LDSM4(a[mt], aPl + aoff[mt] + kb);
        #pragma unroll
        for (int c = 0; c < 2; c++) LDSM4(w[c], wPl + woff[c] + kb);
        #pragma unroll
        for (int mt = 0; mt < 2; mt++) {
            #pragma unroll
            for (int c = 0; c < 2; c++) {
                MMAH(acc[mt][2*c],   a[mt], w[c][0], w[c][1]);
                MMAH(acc[mt][2*c+1], a[mt], w[c][2], w[c][3]);
            }
        }
    }
}

template<int MODE>
__global__ __launch_bounds__(MODE == 0 ? 256 : 512)
void k_gemm(const __half* __restrict__ A1, const __half* __restrict__ A2,
            const __half* __restrict__ Wimg1, const __half* __restrict__ Wimg2,
            const __half* __restrict__ Wimg3,
            const float* __restrict__ bias1, const float* __restrict__ bias2,
            __half* __restrict__ outh, float* __restrict__ outf, int nrows)
{
    constexpr int TM      = (MODE == 0) ? 64  : 128;
    constexpr int THREADS = (MODE == 0) ? 256 : 512;
    constexpr int NWM     = (MODE == 0) ? 2   : 4;     // m-warps (x 4 n-warps)
    constexpr int APLB    = TM * AST * 2;              // A plane bytes

    extern __shared__ char sm[];
    char* Apl1 = sm;
    char* Apl2 = sm + APLB;
    char* W1   = sm + 2*APLB;
    char* W2   = W1 + PLB;
    char* W3   = W2 + PLB;     // MODE 1 only

    int tid = threadIdx.x;
    // copy weight plane(s) into smem once per CTA
    {
        const float4* s1 = (const float4*)Wimg1;
        const float4* s2 = (const float4*)Wimg2;
        float4* d1 = (float4*)W1;
        float4* d2 = (float4*)W2;
        for (int i = tid; i < PLB/16; i += THREADS) { d1[i] = s1[i]; d2[i] = s2[i]; }
        if (MODE == 1) {
            const float4* s3 = (const float4*)Wimg3;
            float4* d3 = (float4*)W3;
            for (int i = tid; i < PLB/16; i += THREADS) d3[i] = s3[i];
        }
    }

    int wid = tid >> 5, lane = tid & 31;
    int wm = wid % NWM, wn = wid / NWM;    // warp tile 32 rows x 32 cols

    uint32_t aoff[2], woff[2];
    {
        int kL = (lane >> 4) * 8;
        #pragma unroll
        for (int mt = 0; mt < 2; mt++) {
            int m = wm*32 + mt*16 + ((lane >> 3) & 1)*8 + (lane & 7);
            aoff[mt] = (uint32_t)(m*AST + kL) * 2u;
        }
        int kW = ((lane >> 3) & 1) * 8;
        #pragma unroll
        for (int c = 0; c < 2; c++) {
            int n = wn*32 + c*16 + (lane >> 4)*8 + (lane & 7);
            woff[c] = (uint32_t)(n*AST + kW) * 2u;
        }
    }
    uint32_t sA1 = smem_u32(Apl1), sA2 = smem_u32(Apl2);
    uint32_t sW1 = smem_u32(W1),   sW2 = smem_u32(W2), sW3 = smem_u32(W3);

    int g = lane >> 2, t4 = lane & 3;
    const int ntiles = (nrows + TM - 1) / TM;

    for (int tile = blockIdx.x; tile < ntiles; tile += gridDim.x) {
        int row0 = tile * TM;

        __syncthreads();                       // prior tile's reads done
        copy_tile_h<TM, THREADS>(A1, Apl1, row0, nrows);
        copy_tile_h<TM, THREADS>(A2, Apl2, row0, nrows);
        __syncthreads();

        float acc[2][4][4];
        #pragma unroll
        for (int a = 0; a < 2; a++)
            #pragma unroll
            for (int b = 0; b < 4; b++)
                #pragma unroll
                for (int c = 0; c < 4; c++) acc[a][b][c] = 0.f;

        pass_dual(acc, sA1, sA2, sW1, sW2, aoff, woff);

        if (MODE == 0) {
            // epilogue: relu(acc + bias1) -> fp16 out
            #pragma unroll
            for (int mt = 0; mt < 2; mt++) {
                int row = row0 + wm*32 + mt*16 + g;
                #pragma unroll
                for (int nt = 0; nt < 4; nt++) {
                    int col = wn*32 + nt*8 + t4*2;
                    float2 bb = *(const float2*)(bias1 + col);
                    float r0 = fmaxf(acc[mt][nt][0] + bb.x, 0.f);
                    float r1 = fmaxf(acc[mt][nt][1] + bb.y, 0.f);
                    float r2 = fmaxf(acc[mt][nt][2] + bb.x, 0.f);
                    float r3 = fmaxf(acc[mt][nt][3] + bb.y, 0.f);
                    if (row < nrows)
                        *(__half2*)(outh + (size_t)row*DD + col) = __floats2half2_rn(r0, r1);
                    if (row + 8 < nrows)
                        *(__half2*)(outh + (size_t)(row + 8)*DD + col) = __floats2half2_rn(r2, r3);
                }
            }
        } else {
            // chained final: t = relu(acc + bias1) -> Apl1 (fp16), then t @ W3^T + bias2
            __syncthreads();    // everyone done reading Apl1/Apl2
            #pragma unroll
            for (int mt = 0; mt < 2; mt++) {
                int r = wm*32 + mt*16 + g;
                #pragma unroll
                for (int nt = 0; nt < 4; nt++) {
                    int col = wn*32 + nt*8 + t4*2;
                    float2 bb = *(const float2*)(bias1 + col);
                    float r0 = fmaxf(acc[mt][nt][0] + bb.x, 0.f);
                    float r1 = fmaxf(acc[mt][nt][1] + bb.y, 0.f);
                    float r2 = fmaxf(acc[mt][nt][2] + bb.x, 0.f);
                    float r3 = fmaxf(acc[mt][nt][3] + bb.y, 0.f);
                    *(__half2*)(Apl1 + ((size_t)r*AST + col)*2)       = __floats2half2_rn(r0, r1);
                    *(__half2*)(Apl1 + ((size_t)(r + 8)*AST + col)*2) = __floats2half2_rn(r2, r3);
                }
            }
            __syncthreads();    // t tile visible to all warps

            float acc2[2][4][4];
            #pragma unroll
            for (int a = 0; a < 2; a++)
                #pragma unroll
                for (int b = 0; b < 4; b++)
                    #pragma unroll
                    for (int c = 0; c < 4; c++) acc2[a][b][c] = 0.f;

            pass_h(acc2, sA1, sW3, aoff, woff);

            #pragma unroll
            for (int mt = 0; mt < 2; mt++) {
                int row = row0 + wm*32 + mt*16 + g;
                #pragma unroll
                for (int nt = 0; nt < 4; nt++) {
                    int col = wn*32 + nt*8 + t4*2;
                    float2 bb = *(const float2*)(bias2 + col);
                    float r0 = acc2[mt][nt][0] + bb.x;
                    float r1 = acc2[mt][nt][1] + bb.y;
                    float r2 = acc2[mt][nt][2] + bb.x;
                    float r3 = acc2[mt][nt][3] + bb.y;
                    if (row < nrows)
                        *(float2*)(outf + (size_t)row*DD + col) = make_float2(r0, r1);
                    if (row + 8 < nrows)
                        *(float2*)(outf + (size_t)(row + 8)*DD + col) = make_float2(r2, r3);
                }
            }
        }
    }
}

// ---------------- launch ----------------
extern "C" void kernel_launch(void* const* d_in, const int* in_sizes, int n_in,
                              void* d_out, int out_size) {
    const float* x  = (const float*)d_in[0];
    const void*  ei = d_in[1];
    const float* Wl = (const float*)d_in[2];
    const float* bl = (const float*)d_in[3];
    const float* Wr = (const float*)d_in[4];
    const float* W  = (const float*)d_in[5];
    const float* b  = (const float*)d_in[6];
    float* out = (float*)d_out;

    void *pxh, *px1h, *pah, *pw;
    cudaGetSymbolAddress(&pxh,  g_xh);
    cudaGetSymbolAddress(&px1h, g_x1h);
    cudaGetSymbolAddress(&pah,  g_aggh);
    cudaGetSymbolAddress(&pw,   g_Wh);
    __half* xh   = (__half*)pxh;
    __half* x1h  = (__half*)px1h;
    __half* aggh = (__half*)pah;
    __half* Wh = (__half*)pw;
    __half* M0 = Wh;            // Wl0
    __half* M1 = Wh + 1*PL;     // Wl1
    __half* M2 = Wh + 2*PL;     // Wr0
    __half* M3 = Wh + 3*PL;     // Wr1
    __half* M4 = Wh + 4*PL;     // W

    const int smem0 = 2*(64*AST*2) + 2*PLB;   // 104448 (2 x 64-row A + 2 W) -> 2 CTAs/SM
    const int smem1 = 2*PLB + 3*PLB;          // 174080 (2 x 128-row A + 3 W)
    cudaFuncSetAttribute(k_gemm<0>, cudaFuncAttributeMaxDynamicSharedMemorySize, smem0);
    cudaFuncSetAttribute(k_gemm<1>, cudaFuncAttributeMaxDynamicSharedMemorySize, smem1);

    // prep: x->fp16, zero cursors, weight fp16 images
    k_prep   <<<CVB + ZB + 5, 512>>>(x, Wl, Wr, W);
    // bucket CSR in one pass
    k_scatter<<<(EE+511)/512, 512>>>(ei);

    // layer 0: relu( max-agg(x) @ Wl0^T + x @ Wr0^T + bl0 ) -> x1h (fp16)
    k_agg_h<<<(NN+7)/8, 256>>>(xh, aggh);
    k_gemm<0><<<296, 256, smem0>>>(aggh, xh, M0, M2, nullptr, bl, nullptr, x1h, nullptr, NN);
    // layer 1 + chained final linear -> out (fp32)
    k_agg_h<<<(NN+7)/8, 256>>>(x1h, aggh);
    k_gemm<1><<<148, 512, smem1>>>(aggh, x1h, M1, M3, M4, bl+DD, b, nullptr, out, NN);
}

// round 17
// speedup vs baseline: 1.0308x; 1.0308x over previous
#include <cuda_runtime.h>
#include <cuda_bf16.h>
#include <cuda_fp16.h>
#include <cstdint>

#define NN 50000
#define EE 800000
#define DD 128
#define NMAT (DD*DD)
#define CAP 96                   // bucket capacity (max degree; Poisson(16) -> safe)
#define CVB 1563                 // x->fp16 conversion blocks
#define ZB  25                   // cursor zero blocks

#define AST 136                  // padded row stride (fp16 elems) -> conflict-free ldmatrix
#define PL  (128*AST)            // plane elems (17408)
#define PLB (PL*2)               // plane bytes (34816)

// ---------------- scratch (static device globals; no runtime alloc) ----------------
__device__ __half g_xh[NN*DD];    // fp16 copy of x
__device__ __half g_x1h[NN*DD];   // fp16 layer-1 activations
__device__ __half g_aggh[NN*DD];  // fp16 aggregation output
__device__ int    g_cursor[NN];   // zeroed by k_prep each run; after scatter holds degree
__device__ int    g_csr[NN*CAP];
__device__ __half g_Wh[5*PL];     // 5 matrices, fp16 plane, padded layout

// ---------------- helpers ----------------
__device__ __forceinline__ uint32_t smem_u32(const void* p) {
    uint32_t a;
    asm("{ .reg .u64 t; cvta.to.shared.u64 t, %1; cvt.u32.u64 %0, t; }" : "=r"(a) : "l"(p));
    return a;
}

#define LDSM4(r, addr) \
    asm volatile("ldmatrix.sync.aligned.m8n8.x4.shared.b16 {%0,%1,%2,%3}, [%4];" \
        : "=r"((r)[0]), "=r"((r)[1]), "=r"((r)[2]), "=r"((r)[3]) : "r"(addr))

#define MMAH(d, a, b0, b1) \
    asm volatile("mma.sync.aligned.m16n8k16.row.col.f32.f16.f16.f32 " \
        "{%0,%1,%2,%3}, {%4,%5,%6,%7}, {%8,%9}, {%0,%1,%2,%3};" \
        : "+f"((d)[0]), "+f"((d)[1]), "+f"((d)[2]), "+f"((d)[3]) \
        : "r"((a)[0]), "r"((a)[1]), "r"((a)[2]), "r"((a)[3]), "r"(b0), "r"(b1))

// per-block edge_index dtype detection (JAX x64-off downcasts int64 -> int32)
__device__ __forceinline__ int detect_is64(const void* __restrict__ ei) {
    __shared__ int s64;
    if (threadIdx.x < 32) {
        const long long* p = (const long long*)ei;
        long long v0 = p[threadIdx.x];
        long long v1 = p[threadIdx.x + 32];
        unsigned ok = (v0 >= 0 && v0 < NN && v1 >= 0 && v1 < NN) ? 1u : 0u;
        unsigned m = __ballot_sync(0xffffffffu, ok);
        if (threadIdx.x == 0) s64 = (m == 0xffffffffu) ? 1 : 0;
    }
    __syncthreads();
    return s64;
}
__device__ __forceinline__ int load_idx(const void* ei, int pos, int is64) {
    if (is64) return (int)((const long long*)ei)[pos];
    return ((const int*)ei)[pos];
}

// ---------------- prep: x->fp16 copy, zero cursor, weight fp16 image ----------------
__global__ void k_prep(const float* __restrict__ x,
                       const float* __restrict__ Wl, const float* __restrict__ Wr,
                       const float* __restrict__ W) {
    int b = blockIdx.x;
    if (b < CVB) {
        int i = (b*512 + threadIdx.x) * 8;
        if (i < NN*DD) {
            float4 v0 = ((const float4*)x)[i/4];
            float4 v1 = ((const float4*)x)[i/4 + 1];
            __half2 h0 = __floats2half2_rn(v0.x, v0.y);
            __half2 h1 = __floats2half2_rn(v0.z, v0.w);
            __half2 h2 = __floats2half2_rn(v1.x, v1.y);
            __half2 h3 = __floats2half2_rn(v1.z, v1.w);
            uint4 o;
            o.x = *(unsigned*)&h0; o.y = *(unsigned*)&h1;
            o.z = *(unsigned*)&h2; o.w = *(unsigned*)&h3;
            ((uint4*)g_xh)[i/8] = o;
        }
    } else if (b < CVB + ZB) {
        int i = ((b - CVB)*512 + threadIdx.x) * 4;
        if (i < NN) ((int4*)g_cursor)[i/4] = make_int4(0,0,0,0);
    } else {
        int m = b - CVB - ZB;   // 0,1=Wl 2,3=Wr 4=W
        const float* src = (m < 2) ? Wl + m*NMAT : ((m < 4) ? Wr + (m-2)*NMAT : W);
        __half* dst = g_Wh + (size_t)m*PL;
        for (int idx = threadIdx.x; idx < NMAT; idx += blockDim.x) {
            int row = idx >> 7, k = idx & 127;
            dst[row*AST + k] = __float2half_rn(src[idx]);
        }
    }
}

// ---------------- bucket scatter (no count/scan needed) ----------------
__global__ void k_scatter(const void* __restrict__ ei) {
    int is64 = detect_is64(ei);
    int i = blockIdx.x*blockDim.x + threadIdx.x;
    if (i < EE) {
        int src = load_idx(ei, i, is64);
        int dst = load_idx(ei, EE + i, is64);
        if ((unsigned)dst < NN && (unsigned)src < NN) {
            int pos = atomicAdd(&g_cursor[dst], 1);
            if (pos < CAP) g_csr[dst*CAP + pos] = src;
        }
    }
}

// ---------------- max-aggregation over fp16 copy: warp per node ----------------
__global__ void k_agg_h(const __half* __restrict__ xh, __half* __restrict__ aggh) {
    int w    = blockIdx.x * 8 + (threadIdx.x >> 5);
    int lane = threadIdx.x & 31;
    if (w >= NN) return;
    int cnt = g_cursor[w];
    if (cnt > CAP) cnt = CAP;
    const int* bucket = g_csr + w*CAP;
    const uint2* xv = (const uint2*)xh;     // 4 fp16 per lane
    const float NEG = __int_as_float(0xff800000);
    float4 m = make_float4(NEG, NEG, NEG, NEG);
    int e = 0;
    for (; e + 8 <= cnt; e += 8) {
        int s0 = bucket[e],   s1 = bucket[e+1], s2 = bucket[e+2], s3 = bucket[e+3];
        int s4 = bucket[e+4], s5 = bucket[e+5], s6 = bucket[e+6], s7 = bucket[e+7];
        uint2 u0 = xv[s0*32 + lane], u1 = xv[s1*32 + lane];
        uint2 u2 = xv[s2*32 + lane], u3 = xv[s3*32 + lane];
        uint2 u4 = xv[s4*32 + lane], u5 = xv[s5*32 + lane];
        uint2 u6 = xv[s6*32 + lane], u7 = xv[s7*32 + lane];
        #pragma unroll
        for (int j = 0; j < 8; j++) {
            uint2 u = (j==0)?u0:(j==1)?u1:(j==2)?u2:(j==3)?u3:(j==4)?u4:(j==5)?u5:(j==6)?u6:u7;
            float2 a = __half22float2(*(__half2*)&u.x);
            float2 bq = __half22float2(*(__half2*)&u.y);
            m.x = fmaxf(m.x, a.x);  m.y = fmaxf(m.y, a.y);
            m.z = fmaxf(m.z, bq.x); m.w = fmaxf(m.w, bq.y);
        }
    }
    for (; e < cnt; e++) {
        uint2 u = xv[bucket[e]*32 + lane];
        float2 a = __half22float2(*(__half2*)&u.x);
        float2 bq = __half22float2(*(__half2*)&u.y);
        m.x = fmaxf(m.x, a.x);  m.y = fmaxf(m.y, a.y);
        m.z = fmaxf(m.z, bq.x); m.w = fmaxf(m.w, bq.y);
    }
    if (cnt == 0) m = make_float4(0.f, 0.f, 0.f, 0.f);
    __half2 h01 = __floats2half2_rn(m.x, m.y);
    __half2 h23 = __floats2half2_rn(m.z, m.w);
    uint2 o;
    o.x = *(unsigned*)&h01; o.y = *(unsigned*)&h23;
    ((uint2*)aggh)[w*32 + lane] = o;
}

// ---------------- all-fp16 tensor-core GEMM, register-prefetch pipelined ----------
// MODE 0: out_h = relu( A1 @ W1^T + A2 @ W2^T + bias1 )                  (fp16 out)
// MODE 1: t = relu( A1 @ W1^T + A2 @ W2^T + bias1 ); out_f = t @ W3^T + bias2 (fp32)
// 512 threads, 16 warps (4x4), warp tile 32x32, persistent grid.
// Next tile's A1 plane is prefetched into registers during MMA, dumped after sync.

__device__ __forceinline__ void copy_tile_h(const __half* __restrict__ src, char* plane,
                                            int row0, int nrows) {
    int tid = threadIdx.x;
    #pragma unroll
    for (int it = 0; it < 4; it++) {
        int fidx = it*512 + tid;            // 2048 uint4s = 128 rows x 16
        int row = fidx >> 4;
        int c   = fidx & 15;
        uint4 v = make_uint4(0,0,0,0);
        if (row0 + row < nrows) v = ((const uint4*)src)[(row0 + row)*16 + c];
        *(uint4*)(plane + row*(AST*2) + c*16) = v;
    }
}

// acc += A1 @ W1^T + A2 @ W2^T, interleaved per k-step
__device__ __forceinline__ void pass_dual(float acc[2][4][4],
                                          uint32_t aPl1, uint32_t aPl2,
                                          uint32_t wPl1, uint32_t wPl2,
                                          const uint32_t* aoff, const uint32_t* woff) {
    #pragma unroll 1
    for (int ks = 0; ks < 8; ks++) {
        uint32_t kb = (uint32_t)ks * 32u;
        uint32_t a1[2][4], a2[2][4], w1[2][4], w2[2][4];
        #pragma unroll
        for (int mt = 0; mt < 2; mt++) {
            LDSM4(a1[mt], aPl1 + aoff[mt] + kb);
            LDSM4(a2[mt], aPl2 + aoff[mt] + kb);
        }
        #pragma unroll
        for (int c = 0; c < 2; c++) {
            LDSM4(w1[c], wPl1 + woff[c] + kb);
            LDSM4(w2[c], wPl2 + woff[c] + kb);
        }
        #pragma unroll
        for (int mt = 0; mt < 2; mt++) {
            #pragma unroll
            for (int c = 0; c < 2; c++) {
                MMAH(acc[mt][2*c],   a1[mt], w1[c][0], w1[c][1]);
                MMAH(acc[mt][2*c+1], a1[mt], w1[c][2], w1[c][3]);
                MMAH(acc[mt][2*c],   a2[mt], w2[c][0], w2[c][1]);
                MMAH(acc[mt][2*c+1], a2[mt], w2[c][2], w2[c][3]);
            }
        }
    }
}

// acc += A @ W^T (single stream; chained W3 pass)
__device__ __forceinline__ void pass_h(float acc[2][4][4],
                                       uint32_t aPl, uint32_t wPl,
                                       const uint32_t* aoff, const uint32_t* woff) {
    #pragma unroll 2
    for (int ks = 0; ks < 8; ks++) {
        uint32_t kb = (uint32_t)ks * 32u;
        uint32_t a[2][4], w[2][4];
        #pragma unroll
        for (int mt = 0; mt < 2; mt++) LDSM4(a[mt], aPl + aoff[mt] + kb);
        #pragma unroll
        for (int c = 0; c < 2; c++) LDSM4(w[c], wPl + woff[c] + kb);
        #pragma unroll
        for (int mt = 0; mt < 2; mt++) {
            #pragma unroll
            for (int c = 0; c < 2; c++) {
                MMAH(acc[mt][2*c],   a[mt], w[c][0], w[c][1]);
                MMAH(acc[mt][2*c+1], a[mt], w[c][2], w[c][3]);
            }
        }
    }
}

template<int MODE>
__global__ __launch_bounds__(512)
void k_gemm(const __half* __restrict__ A1, const __half* __restrict__ A2,
            const __half* __restrict__ Wimg1, const __half* __restrict__ Wimg2,
            const __half* __restrict__ Wimg3,
            const float* __restrict__ bias1, const float* __restrict__ bias2,
            __half* __restrict__ outh, float* __restrict__ outf, int nrows)
{
    extern __shared__ char sm[];
    char* Apl1 = sm;
    char* Apl2 = sm + PLB;
    char* W1   = sm + 2*PLB;
    char* W2   = sm + 3*PLB;
    char* W3   = sm + 4*PLB;     // MODE 1 only

    int tid = threadIdx.x;
    const int ntiles = (nrows + 127) / 128;
    int tile = blockIdx.x;

    // prologue: weights + tile0 A planes, one barrier
    {
        const float4* s1 = (const float4*)Wimg1;
        const float4* s2 = (const float4*)Wimg2;
        float4* d1 = (float4*)W1;
        float4* d2 = (float4*)W2;
        for (int i = tid; i < PLB/16; i += 512) { d1[i] = s1[i]; d2[i] = s2[i]; }
        if (MODE == 1) {
            const float4* s3 = (const float4*)Wimg3;
            float4* d3 = (float4*)W3;
            for (int i = tid; i < PLB/16; i += 512) d3[i] = s3[i];
        }
    }
    if (tile < ntiles) {
        copy_tile_h(A1, Apl1, tile*128, nrows);
        copy_tile_h(A2, Apl2, tile*128, nrows);
    }
    __syncthreads();

    int wid = tid >> 5, lane = tid & 31;
    int wm = wid & 3, wn = wid >> 2;     // 4x4 warps, warp tile 32 rows x 32 cols

    uint32_t aoff[2], woff[2];
    {
        int kL = (lane >> 4) * 8;
        #pragma unroll
        for (int mt = 0; mt < 2; mt++) {
            int m = wm*32 + mt*16 + ((lane >> 3) & 1)*8 + (lane & 7);
            aoff[mt] = (uint32_t)(m*AST + kL) * 2u;
        }
        int kW = ((lane >> 3) & 1) * 8;
        #pragma unroll
        for (int c = 0; c < 2; c++) {
            int n = wn*32 + c*16 + (lane >> 4)*8 + (lane & 7);
            woff[c] = (uint32_t)(n*AST + kW) * 2u;
        }
    }
    uint32_t sA1 = smem_u32(Apl1), sA2 = smem_u32(Apl2);
    uint32_t sW1 = smem_u32(W1),   sW2 = smem_u32(W2), sW3 = smem_u32(W3);

    int g = lane >> 2, t4 = lane & 3;

    for (; tile < ntiles; tile += gridDim.x) {
        int row0 = tile * 128;
        int next = tile + gridDim.x;

        // prefetch next tile's A1 plane into registers (overlaps MMA below)
        uint4 pf[4];
        if (next < ntiles) {
            int nr0 = next * 128;
            #pragma unroll
            for (int it = 0; it < 4; it++) {
                int fidx = it*512 + tid;
                int row = fidx >> 4, c = fidx & 15;
                pf[it] = make_uint4(0,0,0,0);
                if (nr0 + row < nrows) pf[it] = ((const uint4*)A1)[(nr0 + row)*16 + c];
            }
        }

        float acc[2][4][4];
        #pragma unroll
        for (int a = 0; a < 2; a++)
            #pragma unroll
            for (int b = 0; b < 4; b++)
                #pragma unroll
                for (int c = 0; c < 4; c++) acc[a][b][c] = 0.f;

        pass_dual(acc, sA1, sA2, sW1, sW2, aoff, woff);

        if (MODE == 0) {
            // epilogue: relu(acc + bias1) -> fp16 out
            #pragma unroll
            for (int mt = 0; mt < 2; mt++) {
                int row = row0 + wm*32 + mt*16 + g;
                #pragma unroll
                for (int nt = 0; nt < 4; nt++) {
                    int col = wn*32 + nt*8 + t4*2;
                    float2 bb = *(const float2*)(bias1 + col);
                    float r0 = fmaxf(acc[mt][nt][0] + bb.x, 0.f);
                    float r1 = fmaxf(acc[mt][nt][1] + bb.y, 0.f);
                    float r2 = fmaxf(acc[mt][nt][2] + bb.x, 0.f);
                    float r3 = fmaxf(acc[mt][nt][3] + bb.y, 0.f);
                    if (row < nrows)
                        *(__half2*)(outh + (size_t)row*DD + col) = __floats2half2_rn(r0, r1);
                    if (row + 8 < nrows)
                        *(__half2*)(outh + (size_t)(row + 8)*DD + col) = __floats2half2_rn(r2, r3);
                }
            }
        } else {
            // chained final: t = relu(acc + bias1) -> Apl1 (fp16), then t @ W3^T + bias2
            __syncthreads();    // everyone done reading Apl1/Apl2
            #pragma unroll
            for (int mt = 0; mt < 2; mt++) {
                int r = wm*32 + mt*16 + g;
                #pragma unroll
                for (int nt = 0; nt < 4; nt++) {
                    int col = wn*32 + nt*8 + t4*2;
                    float2 bb = *(const float2*)(bias1 + col);
                    float r0 = fmaxf(acc[mt][nt][0] + bb.x, 0.f);
                    float r1 = fmaxf(acc[mt][nt][1] + bb.y, 0.f);
                    float r2 = fmaxf(acc[mt][nt][2] + bb.x, 0.f);
                    float r3 = fmaxf(acc[mt][nt][3] + bb.y, 0.f);
                    *(__half2*)(Apl1 + ((size_t)r*AST + col)*2)       = __floats2half2_rn(r0, r1);
                    *(__half2*)(Apl1 + ((size_t)(r + 8)*AST + col)*2) = __floats2half2_rn(r2, r3);
                }
            }
            __syncthreads();    // t tile visible to all warps

            float acc2[2][4][4];
            #pragma unroll
            for (int a = 0; a < 2; a++)
                #pragma unroll
                for (int b = 0; b < 4; b++)
                    #pragma unroll
                    for (int c = 0; c < 4; c++) acc2[a][b][c] = 0.f;

            pass_h(acc2, sA1, sW3, aoff, woff);

            #pragma unroll
            for (int mt = 0; mt < 2; mt++) {
                int row = row0 + wm*32 + mt*16 + g;
                #pragma unroll
                for (int nt = 0; nt < 4; nt++) {
                    int col = wn*32 + nt*8 + t4*2;
                    float2 bb = *(const float2*)(bias2 + col);
                    float r0 = acc2[mt][nt][0] + bb.x;
                    float r1 = acc2[mt][nt][1] + bb.y;
                    float r2 = acc2[mt][nt][2] + bb.x;
                    float r3 = acc2[mt][nt][3] + bb.y;
                    if (row < nrows)
                        *(float2*)(outf + (size_t)row*DD + col) = make_float2(r0, r1);
                    if (row + 8 < nrows)
                        *(float2*)(outf + (size_t)(row + 8)*DD + col) = make_float2(r2, r3);
                }
            }
        }

        __syncthreads();   // all warps done reading planes (and t tile in MODE 1)
        if (next < ntiles) {
            // dump prefetched A1, copy A2 synchronously
            #pragma unroll
            for (int it = 0; it < 4; it++) {
                int fidx = it*512 + tid;
                int row = fidx >> 4, c = fidx & 15;
                *(uint4*)(Apl1 + row*(AST*2) + c*16) = pf[it];
            }
            copy_tile_h(A2, Apl2, next*128, nrows);
        }
        __syncthreads();
    }
}

// ---------------- launch ----------------
extern "C" void kernel_launch(void* const* d_in, const int* in_sizes, int n_in,
                              void* d_out, int out_size) {
    const float* x  = (const float*)d_in[0];
    const void*  ei = d_in[1];
    const float* Wl = (const float*)d_in[2];
    const float* bl = (const float*)d_in[3];
    const float* Wr = (const float*)d_in[4];
    const float* W  = (const float*)d_in[5];
    const float* b  = (const float*)d_in[6];
    float* out = (float*)d_out;

    void *pxh, *px1h, *pah, *pw;
    cudaGetSymbolAddress(&pxh,  g_xh);
    cudaGetSymbolAddress(&px1h, g_x1h);
    cudaGetSymbolAddress(&pah,  g_aggh);
    cudaGetSymbolAddress(&pw,   g_Wh);
    __half* xh   = (__half*)pxh;
    __half* x1h  = (__half*)px1h;
    __half* aggh = (__half*)pah;
    __half* Wh = (__half*)pw;
    __half* M0 = Wh;            // Wl0
    __half* M1 = Wh + 1*PL;     // Wl1
    __half* M2 = Wh + 2*PL;     // Wr0
    __half* M3 = Wh + 3*PL;     // Wr1
    __half* M4 = Wh + 4*PL;     // W

    const int smem4 = 4*PLB;   // 139264  (2 A + 2 W)
    const int smem5 = 5*PLB;   // 174080  (2 A + 3 W)
    cudaFuncSetAttribute(k_gemm<0>, cudaFuncAttributeMaxDynamicSharedMemorySize, smem4);
    cudaFuncSetAttribute(k_gemm<1>, cudaFuncAttributeMaxDynamicSharedMemorySize, smem5);

    // prep: x->fp16, zero cursors, weight fp16 images
    k_prep   <<<CVB + ZB + 5, 512>>>(x, Wl, Wr, W);
    // bucket CSR in one pass
    k_scatter<<<(EE+511)/512, 512>>>(ei);

    // layer 0: relu( max-agg(x) @ Wl0^T + x @ Wr0^T + bl0 ) -> x1h (fp16)
    k_agg_h<<<(NN+7)/8, 256>>>(xh, aggh);
    k_gemm<0><<<148, 512, smem4>>>(aggh, xh, M0, M2, nullptr, bl, nullptr, x1h, nullptr, NN);
    // layer 1 + chained final linear -> out (fp32)
    k_agg_h<<<(NN+7)/8, 256>>>(x1h, aggh);
    k_gemm<1><<<148, 512, smem5>>>(aggh, x1h, M1, M3, M4, bl+DD, b, nullptr, out, NN);
}